// round 7
// baseline (speedup 1.0000x reference)
#include <cuda_runtime.h>
#include <cuda_bf16.h>

// Problem constants
#define B_      2
#define L_      64
#define D_      1024
#define H_      512
#define S_      50000
#define V_      40000
#define K_      32
#define M_      128          // B_*L_
#define SLM_SCALE 0.1f
#define BN_EPS  1e-5f

// ---------------- scratch (device globals; no allocation allowed) ----------------
__device__ float g_scale[L_];
__device__ float g_shift[L_];
__device__ __align__(16) float g_ht[H_ * M_];          // h^T : [512][128]
__device__ __align__(16) float g_vt[V_ * M_];          // v^T : [40000][128] (20.5 MB)

// ---------------- Kernel 1: BatchNorm stats over (B, D) per position l ----------------
__global__ __launch_bounds__(256)
void bn_stats_kernel(const float* __restrict__ x,
                     const float* __restrict__ gamma,
                     const float* __restrict__ beta)
{
    const int l = blockIdx.x;
    const float* p0 = x + (size_t)l * D_;             // b = 0
    const float* p1 = x + (size_t)(L_ + l) * D_;      // b = 1
    float s = 0.f, sq = 0.f;
    for (int i = threadIdx.x; i < D_; i += 256) {
        float a = p0[i], b = p1[i];
        s  += a + b;
        sq += a * a + b * b;
    }
    __shared__ float rs[256], rq[256];
    rs[threadIdx.x] = s; rq[threadIdx.x] = sq;
    __syncthreads();
    for (int off = 128; off > 0; off >>= 1) {
        if (threadIdx.x < off) {
            rs[threadIdx.x] += rs[threadIdx.x + off];
            rq[threadIdx.x] += rq[threadIdx.x + off];
        }
        __syncthreads();
    }
    if (threadIdx.x == 0) {
        const float inv_n = 1.f / (float)(B_ * D_);
        float mean = rs[0] * inv_n;
        float var  = rq[0] * inv_n - mean * mean;
        float rstd = rsqrtf(var + BN_EPS);
        float sc = gamma[l] * rstd;
        g_scale[l] = sc;
        g_shift[l] = beta[l] - mean * sc;
    }
}

// ---------------- Kernel 2: h = relu(xn @ W1 + b1), stored transposed ----------------
// grid (2, 16), 256 threads. Tile M=64, N=32, KC=32. Thread tile 4m x 2n.
__global__ __launch_bounds__(256)
void h_gemm_kernel(const float* __restrict__ x,
                   const float* __restrict__ W1,
                   const float* __restrict__ b1)
{
    __shared__ float sSc[64], sSh[64];
    __shared__ float Ast[64 * 33];    // [mi][ki], padded
    __shared__ float Bst[32 * 32];    // [ki][ni]
    const int tid = threadIdx.x;
    const int m0 = blockIdx.x * 64;   // 0 or 64
    const int n0 = blockIdx.y * 32;
    if (tid < 64) { sSc[tid] = g_scale[tid]; sSh[tid] = g_shift[tid]; }
    __syncthreads();
    const int mg = tid >> 4;          // 0..15
    const int ng = tid & 15;          // 0..15
    float acc[4][2] = {};
    for (int k0 = 0; k0 < D_; k0 += 32) {
        // A tile 64x32: affine(x)
        #pragma unroll
        for (int i = 0; i < 8; ++i) {
            int e = tid + i * 256;
            int mi = e >> 5, ki = e & 31;
            // l == mi because m0 is a multiple of 64
            float v = x[(size_t)(m0 + mi) * D_ + k0 + ki];
            Ast[mi * 33 + ki] = v * sSc[mi] + sSh[mi];
        }
        // B tile 32x32
        #pragma unroll
        for (int i = 0; i < 4; ++i) {
            int e = tid + i * 256;
            int ki = e >> 5, ni = e & 31;
            Bst[ki * 32 + ni] = W1[(size_t)(k0 + ki) * H_ + n0 + ni];
        }
        __syncthreads();
        #pragma unroll
        for (int kk = 0; kk < 32; ++kk) {
            float b0 = Bst[kk * 32 + ng * 2];
            float b1v = Bst[kk * 32 + ng * 2 + 1];
            #pragma unroll
            for (int i = 0; i < 4; ++i) {
                float a = Ast[(mg * 4 + i) * 33 + kk];
                acc[i][0] = fmaf(a, b0, acc[i][0]);
                acc[i][1] = fmaf(a, b1v, acc[i][1]);
            }
        }
        __syncthreads();
    }
    #pragma unroll
    for (int j = 0; j < 2; ++j) {
        int n = n0 + ng * 2 + j;
        float bb = b1[n];
        #pragma unroll
        for (int i = 0; i < 4; ++i) {
            int m = m0 + mg * 4 + i;
            float hv = acc[i][j] + bb;
            g_ht[(size_t)n * M_ + m] = fmaxf(hv, 0.f);
        }
    }
}

// ---------------- Kernels 3 & 4: big skinny GEMMs (M=128 full, N tile=64, KC=16) ------
// 128 threads, thread tile 8m x 8n.
// MODE 0: v^T = (h @ W_slm + b_slm)^T   -> g_vt
// MODE 1: out = h @ W2 + b2 + 0.1 * gather(v^T)   (fused epilogue)
template<int MODE>
__global__ __launch_bounds__(128)
void big_gemm_kernel(const float* __restrict__ W,
                     const float* __restrict__ bias,
                     const float* __restrict__ slw,
                     const int*   __restrict__ slidx,
                     float* __restrict__ out,
                     int Nfull)
{
    constexpr int KC = 16;
    __shared__ __align__(16) float sAB[(MODE == 1) ? (128 * 65) : (KC * 128 + KC * 64)];
    __shared__ int   sIdx[4][32];
    __shared__ float sWt[4][32];
    float* Ast = sAB;                 // KC x 128 (k-major; contiguous slab of g_ht)
    float* Bst = sAB + KC * 128;      // KC x 64

    const int tid = threadIdx.x;
    const int r = tid >> 3;           // 0..15 -> m base r*8
    const int c = tid & 7;            // 0..7  -> n base c*8
    const int n0 = blockIdx.x * 64;

    float acc[8][8];
    #pragma unroll
    for (int i = 0; i < 8; ++i)
        #pragma unroll
        for (int j = 0; j < 8; ++j) acc[i][j] = 0.f;

    for (int k0 = 0; k0 < H_; k0 += KC) {
        // A tile: single contiguous copy (g_ht is [k][m])
        const float4* Ag = (const float4*)(g_ht + (size_t)k0 * M_);
        float4* A4 = (float4*)Ast;
        #pragma unroll
        for (int i = 0; i < 4; ++i) A4[tid + i * 128] = Ag[tid + i * 128];
        // B tile: KC rows x 64 cols, guarded on N edge
        float4* B4 = (float4*)Bst;
        #pragma unroll
        for (int i = 0; i < 2; ++i) {
            int e = tid + i * 128;            // 0..255
            int ki = e >> 4;                  // 0..15
            int n  = n0 + (e & 15) * 4;
            float4 bv = make_float4(0.f, 0.f, 0.f, 0.f);
            if (MODE == 0 || n < Nfull)
                bv = *(const float4*)(W + (size_t)(k0 + ki) * Nfull + n);
            B4[e] = bv;
        }
        __syncthreads();
        const float4* A4c = (const float4*)Ast;
        const float4* B4c = (const float4*)Bst;
        #pragma unroll
        for (int kk = 0; kk < KC; ++kk) {
            float4 a0 = A4c[kk * 32 + r * 2];
            float4 a1 = A4c[kk * 32 + r * 2 + 1];
            float4 b0 = B4c[kk * 16 + c * 2];
            float4 b1v = B4c[kk * 16 + c * 2 + 1];
            float av[8] = {a0.x, a0.y, a0.z, a0.w, a1.x, a1.y, a1.z, a1.w};
            float bv[8] = {b0.x, b0.y, b0.z, b0.w, b1v.x, b1v.y, b1v.z, b1v.w};
            #pragma unroll
            for (int i = 0; i < 8; ++i)
                #pragma unroll
                for (int j = 0; j < 8; ++j)
                    acc[i][j] = fmaf(av[i], bv[j], acc[i][j]);
        }
        __syncthreads();
    }

    if (MODE == 0) {
        // store v^T (+ b_slm). N=40000 is an exact multiple of 64: no guards.
        #pragma unroll
        for (int j = 0; j < 8; ++j) {
            int n = n0 + c * 8 + j;
            float bs = bias[n];
            float4 v0 = make_float4(acc[0][j] + bs, acc[1][j] + bs,
                                    acc[2][j] + bs, acc[3][j] + bs);
            float4 v1 = make_float4(acc[4][j] + bs, acc[5][j] + bs,
                                    acc[6][j] + bs, acc[7][j] + bs);
            float* dst = g_vt + (size_t)n * M_ + r * 8;
            *(float4*)dst       = v0;
            *(float4*)(dst + 4) = v1;
        }
    } else {
        // ---- fused epilogue: y -> smem, sparse gather-add, coalesced store ----
        float* Cs = sAB;  // 128 x 65 (padded)
        #pragma unroll
        for (int i = 0; i < 8; ++i)
            #pragma unroll
            for (int j = 0; j < 8; ++j)
                Cs[(r * 8 + i) * 65 + c * 8 + j] = acc[i][j];
        __syncthreads();

        const int w = tid >> 5, ln = tid & 31;
        for (int si = 0; si < 16; ++si) {
            int nl = w * 16 + si;
            int s = n0 + nl;
            if (s < Nfull) {                      // warp-uniform
                sIdx[w][ln] = slidx[(size_t)s * K_ + ln];
                sWt[w][ln]  = slw  [(size_t)s * K_ + ln];
                __syncwarp();
                float ax = 0.f, ay = 0.f, az = 0.f, aw = 0.f;
                #pragma unroll
                for (int k = 0; k < K_; ++k) {
                    int   ix = sIdx[w][k];
                    float wk = sWt[w][k];
                    // 512B coalesced across the warp (lane ln covers m = 4*ln..4*ln+3)
                    float4 vv = *(const float4*)(g_vt + (size_t)ix * M_ + ln * 4);
                    ax = fmaf(wk, vv.x, ax);
                    ay = fmaf(wk, vv.y, ay);
                    az = fmaf(wk, vv.z, az);
                    aw = fmaf(wk, vv.w, aw);
                }
                int mB = ln * 4;
                Cs[(mB + 0) * 65 + nl] += SLM_SCALE * ax;
                Cs[(mB + 1) * 65 + nl] += SLM_SCALE * ay;
                Cs[(mB + 2) * 65 + nl] += SLM_SCALE * az;
                Cs[(mB + 3) * 65 + nl] += SLM_SCALE * aw;
                __syncwarp();
            }
        }
        __syncthreads();
        // coalesced final store: out[m*S + n] = y + b2 + 0.1*slm
        for (int e = tid; e < 128 * 64; e += 128) {
            int m = e >> 6, nl = e & 63;
            int n = n0 + nl;
            if (n < Nfull)
                out[(size_t)m * Nfull + n] = Cs[m * 65 + nl] + bias[n];
        }
    }
}

// ---------------- launch ----------------
extern "C" void kernel_launch(void* const* d_in, const int* in_sizes, int n_in,
                              void* d_out, int out_size)
{
    const float* x     = (const float*)d_in[0];   // cached_embeddings [2,64,1024]
    const float* gamma = (const float*)d_in[1];   // bn_gamma [64]
    const float* beta  = (const float*)d_in[2];   // bn_beta  [64]
    const float* W1    = (const float*)d_in[3];   // [1024,512]
    const float* b1    = (const float*)d_in[4];   // [512]
    const float* W2    = (const float*)d_in[5];   // [512,50000]
    const float* b2    = (const float*)d_in[6];   // [50000]
    const float* Wslm  = (const float*)d_in[7];   // [512,40000]
    const float* bslm  = (const float*)d_in[8];   // [40000]
    const float* slw   = (const float*)d_in[9];   // [50000,32]
    const int*   slidx = (const int*)d_in[10];    // [50000,32]
    float* out = (float*)d_out;

    bn_stats_kernel<<<L_, 256>>>(x, gamma, beta);
    h_gemm_kernel<<<dim3(2, 16), 256>>>(x, W1, b1);
    big_gemm_kernel<0><<<V_ / 64, 128>>>(Wslm, bslm, nullptr, nullptr, nullptr, V_);
    big_gemm_kernel<1><<<(S_ + 63) / 64, 128>>>(W2, b2, slw, slidx, out, S_);
}